// round 12
// baseline (speedup 1.0000x reference)
#include <cuda_runtime.h>
#include <cuda_fp16.h>
#include <cstdint>

// ---------------- problem constants ----------------
#define TT      4096
#define CIN     256
#define COUT    256
#define BBATCH  8
#define SGATE   (BBATCH*COUT*TT)     // 8388608

// GEMM tiling
#define BM      128
#define BN      256
#define BK      32
#define NKT     16                    // K=512 / 32
#define ROWB    96                    // smem row stride bytes (24 words) conflict-free
#define STAGEB  ((BM+BN)*ROWB)        // 36864 bytes per stage (A + B)
#define NSTAGE  3
#define GEMM_SMEM (NSTAGE*STAGEB)     // 110592

// ---------------- scratch (__device__ globals; alloc-free rule) -------------
__device__ __align__(128) __half2 g_fz[SGATE];                  // (.x=f, .y=i*z) fp16
__device__ __align__(128) __half  g_o [SGATE];                  // o fp16
__device__ __align__(128) __half  xT  [(size_t)BBATCH*TT*CIN];  // [b][t][cin'] perm fp16
__device__ __align__(128) __half  Wp  [8*NKT*BM*BK];            // [y][kt][m][k'] perm fp16

// ---------------- helpers ----------------
__device__ __forceinline__ float sigm(float v)    { return 1.f / (1.f + __expf(-v)); }
__device__ __forceinline__ float tanh_acc(float v){ return 2.f / (1.f + __expf(-2.f*v)) - 1.f; }
__device__ __forceinline__ uint32_t smem_u32(const void* p) {
    uint32_t a;
    asm("{ .reg .u64 t; cvta.to.shared.u64 t, %1; cvt.u32.u64 %0, t; }" : "=r"(a) : "l"(p));
    return a;
}
// inverse of the frag interleave: dest slot j' (0..15) -> source k-in-16
__device__ __forceinline__ int invp(int jp) {
    int t4 = jp >> 2, pos = jp & 3;
    return 2 * t4 + (pos & 1) + 8 * (pos >> 1);
}

// ---------------------------------------------------------------------------
// Pre-kernel 1: x [b][cin][t] -> xT [b][t][cin'] fp16, k-interleaved per 16
// ---------------------------------------------------------------------------
__global__ __launch_bounds__(256)
void k_xprep(const float* __restrict__ x)
{
    __shared__ float s[32][33];
    const int t0 = blockIdx.x * 32, c0 = blockIdx.y * 32, b = blockIdx.z;
    const int lane = threadIdx.x & 31;

    #pragma unroll
    for (int rr = threadIdx.x >> 5; rr < 32; rr += 8)
        s[rr][lane] = x[((size_t)(b * CIN + c0 + rr)) * TT + t0 + lane];
    __syncthreads();

    #pragma unroll
    for (int i = 0; i < 2; i++) {
        int sl = threadIdx.x + i * 256;       // 512 u32 slots: 32 trow x 16
        int trow = sl >> 4, ms = sl & 15;
        int grp = ms >> 3, jp = (2 * ms) & 15;
        int c0s = grp * 16 + invp(jp);
        int c1s = grp * 16 + invp(jp + 1);
        __half2 v = __floats2half2_rn(s[c0s][trow], s[c1s][trow]);
        ((__half2*)xT)[(((size_t)(b * TT + t0 + trow)) * CIN + c0 >> 1) + ms] = v;
    }
}

// ---------------------------------------------------------------------------
// Pre-kernel 2: W [1024][256][2] -> Wp [y][kt][m][k'] fp16 (permute+interleave)
// ---------------------------------------------------------------------------
__global__ __launch_bounds__(256)
void k_wprep(const float* __restrict__ W)
{
    const int kt = blockIdx.x, y = blockIdx.y;
    __half2* dst = (__half2*)(Wp + ((size_t)(y * NKT + kt) << 12));
    #pragma unroll
    for (int i = 0; i < 8; i++) {
        int sl = threadIdx.x + i * 256;       // 2048 u32 slots: 128 m x 16
        int m = sl >> 4, ms = sl & 15;
        int grp = ms >> 3, jp = (2 * ms) & 15;
        int wrow = (m >> 5) * 256 + y * 32 + (m & 31);
        int kk0 = kt * 32 + grp * 16 + invp(jp);
        int kk1 = kt * 32 + grp * 16 + invp(jp + 1);
        float v0 = W[wrow * 512 + ((kk0 & 255) << 1) + (kk0 >> 8)];
        float v1 = W[wrow * 512 + ((kk1 & 255) << 1) + (kk1 >> 8)];
        dst[sl] = __floats2half2_rn(v0, v1);
    }
}

// ---------------------------------------------------------------------------
// Kernel 3: BM128 x BN256 fp16 mma.sync GEMM, 512 threads, 3-stage pipeline.
//   16 warps: warp_m = wid&3 (gate), warp_n = wid>>2 (n64 subtile).
// ---------------------------------------------------------------------------
__global__ __launch_bounds__(512, 1)
void qrnn_gemm(const float* __restrict__ bias)
{
    extern __shared__ char smem[];
    __shared__ float bias_s[BM];

    const int tid    = threadIdx.x;
    const int lane   = tid & 31;
    const int wid    = tid >> 5;
    const int warp_m = wid & 3;          // gate 0:Z 1:F 2:O 3:I
    const int warp_n = wid >> 2;         // 0..3
    const int g4     = lane >> 2;
    const int t4     = lane & 3;

    const int y   = blockIdx.x;          // y fastest: same-B CTAs adjacent (L2)
    const int oc0 = y * 32;
    const int nt  = blockIdx.y;          // 0..127
    const int b   = nt >> 4;
    const int t0  = (nt & 15) * BN;

    if (tid < BM)
        bias_s[tid] = bias[(tid >> 5) * 256 + oc0 + (tid & 31)];

    float acc[2][8][4];
    #pragma unroll
    for (int im = 0; im < 2; im++)
        #pragma unroll
        for (int in = 0; in < 8; in++)
            #pragma unroll
            for (int ci = 0; ci < 4; ci++) acc[im][in][ci] = 0.f;

    // per-thread cp.async: 1536 16B chunks (A 512 + B 1024), 3 per thread
    #define PREFETCH(KT, BUF) do {                                              \
        const int kt_ = (KT);                                                   \
        char* stA_ = smem + (BUF) * STAGEB;                                     \
        char* stB_ = stA_ + BM * ROWB;                                          \
        const __half* wc_ = Wp + ((size_t)(y * NKT + kt_) << 12);               \
        const int tap_  = (kt_ < 8) ? 1 : 0;                                    \
        const int cin0_ = (kt_ & 7) * 32;                                       \
        _Pragma("unroll")                                                       \
        for (int i_ = 0; i_ < 3; i_++) {                                        \
            int u_ = tid + i_ * 512;                                            \
            if (u_ < 512) {                                                     \
                int r_ = u_ >> 2, cu_ = u_ & 3;                                 \
                uint32_t da_ = smem_u32(stA_ + r_ * ROWB + cu_ * 16);           \
                asm volatile("cp.async.cg.shared.global [%0], [%1], 16;"        \
                    :: "r"(da_), "l"(wc_ + r_ * 32 + cu_ * 8) : "memory");      \
            } else {                                                            \
                int v_ = u_ - 512, r_ = v_ >> 2, cu_ = v_ & 3;                  \
                uint32_t db_ = smem_u32(stB_ + r_ * ROWB + cu_ * 16);           \
                int tg_ = t0 + r_ - tap_;                                       \
                int sz_ = (tg_ >= 0) ? 16 : 0;                                  \
                const __half* src_ = xT + ((size_t)(b * TT + tg_) * CIN + cin0_ + cu_ * 8); \
                asm volatile("cp.async.cg.shared.global [%0], [%1], 16, %2;"    \
                    :: "r"(db_), "l"(src_), "r"(sz_) : "memory");               \
            }                                                                   \
        }                                                                       \
        asm volatile("cp.async.commit_group;" ::: "memory");                    \
    } while (0)

    PREFETCH(0, 0);
    PREFETCH(1, 1);

    #pragma unroll 1
    for (int kt = 0; kt < NKT; kt++) {
        if (kt == NKT - 1) asm volatile("cp.async.wait_group 0;" ::: "memory");
        else               asm volatile("cp.async.wait_group 1;" ::: "memory");
        __syncthreads();   // stage kt visible; stage (kt+2)%3 free for reuse
        if (kt + 2 < NKT) PREFETCH(kt + 2, (kt + 2) % 3);

        const char* As = smem + (kt % 3) * STAGEB;
        const char* Bs = As + BM * ROWB;
        const int row0 = warp_m * 32 + g4;
        const int col0 = warp_n * 64 + g4;

        #pragma unroll
        for (int s = 0; s < 2; s++) {
            const int kb = s * 32 + t4 * 8;
            uint2 a00 = *(const uint2*)(As + (row0     ) * ROWB + kb);
            uint2 a08 = *(const uint2*)(As + (row0 +  8) * ROWB + kb);
            uint2 a16 = *(const uint2*)(As + (row0 + 16) * ROWB + kb);
            uint2 a24 = *(const uint2*)(As + (row0 + 24) * ROWB + kb);
            uint2 bv[8];
            #pragma unroll
            for (int in = 0; in < 8; in++)
                bv[in] = *(const uint2*)(Bs + (col0 + in * 8) * ROWB + kb);
            #pragma unroll
            for (int in = 0; in < 8; in++) {
                asm volatile(
                    "mma.sync.aligned.m16n8k16.row.col.f32.f16.f16.f32 "
                    "{%0,%1,%2,%3}, {%4,%5,%6,%7}, {%8,%9}, {%0,%1,%2,%3};\n"
                    : "+f"(acc[0][in][0]), "+f"(acc[0][in][1]),
                      "+f"(acc[0][in][2]), "+f"(acc[0][in][3])
                    : "r"(a00.x), "r"(a08.x), "r"(a00.y), "r"(a08.y),
                      "r"(bv[in].x), "r"(bv[in].y));
                asm volatile(
                    "mma.sync.aligned.m16n8k16.row.col.f32.f16.f16.f32 "
                    "{%0,%1,%2,%3}, {%4,%5,%6,%7}, {%8,%9}, {%0,%1,%2,%3};\n"
                    : "+f"(acc[1][in][0]), "+f"(acc[1][in][1]),
                      "+f"(acc[1][in][2]), "+f"(acc[1][in][3])
                    : "r"(a16.x), "r"(a24.x), "r"(a16.y), "r"(a24.y),
                      "r"(bv[in].x), "r"(bv[in].y));
            }
        }
    }
    #undef PREFETCH
    __syncthreads();   // all MMA reads done before smem reuse as staging

    // ---- Epilogue: two 128-col rounds; 4 gate buffers per round. ----
    #define BSTRIDE 132
    #pragma unroll 1
    for (int h = 0; h < 2; h++) {
        if ((warp_n >> 1) == h) {
            float* St = (float*)smem + warp_m * (32 * BSTRIDE);
            const int cbase = (warp_n & 1) * 64;
            #pragma unroll
            for (int im = 0; im < 2; im++)
                #pragma unroll
                for (int in = 0; in < 8; in++)
                    #pragma unroll
                    for (int ci = 0; ci < 4; ci++) {
                        int r  = im * 16 + g4 + ((ci >> 1) << 3);
                        int cc = cbase + in * 8 + (t4 << 1) + (ci & 1);
                        float v = acc[im][in][ci] + bias_s[warp_m * 32 + r];
                        v = (warp_m == 0) ? tanh_acc(v) : sigm(v);
                        St[r * BSTRIDE + cc] = v;
                    }
        }
        __syncthreads();
        {
            const float* Sz = (float*)smem;
            const float* Sf = Sz + 32 * BSTRIDE;
            const float* So = Sz + 2 * (32 * BSTRIDE);
            const float* Si = Sz + 3 * (32 * BSTRIDE);
            #pragma unroll
            for (int i = 0; i < 8; i++) {
                int e = tid + i * 512;          // 4096 = 32 rows x 128 cols
                int r = e >> 7, cc = e & 127;
                int sidx = r * BSTRIDE + cc;
                size_t gidx = ((size_t)(b * COUT + oc0 + r)) * TT + t0 + h * 128 + cc;
                g_fz[gidx] = __floats2half2_rn(Sf[sidx], Sz[sidx] * Si[sidx]);
                g_o [gidx] = __float2half_rn(So[sidx]);
            }
        }
        __syncthreads();
    }
    #undef BSTRIDE
}

// ---------------------------------------------------------------------------
// Kernel 4: linear recurrence scan over fp16 packed gates (R10-proven).
//   256 threads/block, 16 elems/thread. c_t = f*c + iz ; H = o*c
// ---------------------------------------------------------------------------
__global__ __launch_bounds__(256)
void qrnn_scan(float* __restrict__ out)
{
    __shared__ float wa[8], wb[8];

    const int tid  = threadIdx.x;
    const int lane = tid & 31;
    const int wrp  = tid >> 5;
    const size_t my = (size_t)blockIdx.x * TT + tid * 16;

    float f[16], z[16];
    #pragma unroll
    for (int q = 0; q < 4; q++) {
        uint4 v = ((const uint4*)(g_fz + my))[q];
        float2 p0 = __half22float2(*(const __half2*)&v.x);
        float2 p1 = __half22float2(*(const __half2*)&v.y);
        float2 p2 = __half22float2(*(const __half2*)&v.z);
        float2 p3 = __half22float2(*(const __half2*)&v.w);
        f[q*4+0] = p0.x; z[q*4+0] = p0.y;
        f[q*4+1] = p1.x; z[q*4+1] = p1.y;
        f[q*4+2] = p2.x; z[q*4+2] = p2.y;
        f[q*4+3] = p3.x; z[q*4+3] = p3.y;
    }

    float a = 1.f, bb = 0.f;
    #pragma unroll
    for (int j = 0; j < 16; j++) { a *= f[j]; bb = f[j] * bb + z[j]; }

    #pragma unroll
    for (int d = 1; d < 32; d <<= 1) {
        float ua = __shfl_up_sync(0xffffffffu, a,  d);
        float ub = __shfl_up_sync(0xffffffffu, bb, d);
        if (lane >= d) { bb = a * ub + bb; a = a * ua; }
    }
    if (lane == 31) { wa[wrp] = a; wb[wrp] = bb; }
    __syncthreads();
    float pb = 0.f;
    #pragma unroll
    for (int w = 0; w < 7; w++)
        if (w < wrp) pb = wa[w] * pb + wb[w];
    float ea = __shfl_up_sync(0xffffffffu, a,  1);
    float eb = __shfl_up_sync(0xffffffffu, bb, 1);
    if (lane == 0) { ea = 1.f; eb = 0.f; }
    float c = ea * pb + eb;              // carry into this chunk (c_init = 0)

    #pragma unroll
    for (int j = 0; j < 16; j++) { c = f[j] * c + z[j]; f[j] = c; }

    uint4 o0 = ((const uint4*)(g_o + my))[0];
    uint4 o1 = ((const uint4*)(g_o + my))[1];
    float ov[16];
    {
        const uint32_t* w0 = (const uint32_t*)&o0;
        const uint32_t* w1 = (const uint32_t*)&o1;
        #pragma unroll
        for (int q = 0; q < 4; q++) {
            float2 p = __half22float2(*(const __half2*)&w0[q]);
            ov[q*2+0] = p.x; ov[q*2+1] = p.y;
        }
        #pragma unroll
        for (int q = 0; q < 4; q++) {
            float2 p = __half22float2(*(const __half2*)&w1[q]);
            ov[8+q*2+0] = p.x; ov[8+q*2+1] = p.y;
        }
    }

    #pragma unroll
    for (int j = 0; j < 4; j++) {
        float4 r;
        r.x = ov[j*4+0] * f[j*4+0]; r.y = ov[j*4+1] * f[j*4+1];
        r.z = ov[j*4+2] * f[j*4+2]; r.w = ov[j*4+3] * f[j*4+3];
        ((float4*)(out + my))[j] = r;
    }
}

extern "C" void kernel_launch(void* const* d_in, const int* in_sizes, int n_in,
                              void* d_out, int out_size)
{
    const float* x    = (const float*)d_in[0];  // [8, 256, 4096]
    const float* W    = (const float*)d_in[1];  // [1024, 256, 2]
    const float* bias = (const float*)d_in[2];  // [1024]
    float* out = (float*)d_out;                 // [8, 256, 4096]

    static int smem_set = 0;
    if (!smem_set) {
        cudaFuncSetAttribute(qrnn_gemm, cudaFuncAttributeMaxDynamicSharedMemorySize, GEMM_SMEM);
        smem_set = 1;
    }

    k_xprep<<<dim3(TT / 32, CIN / 32, BBATCH), 256>>>(x);
    k_wprep<<<dim3(NKT, 8), 256>>>(W);
    qrnn_gemm<<<dim3(8, BBATCH * TT / BN), 512, GEMM_SMEM>>>(bias);
    qrnn_scan<<<BBATCH * COUT, 256>>>(out);
}

// round 13
// speedup vs baseline: 1.3684x; 1.3684x over previous
#include <cuda_runtime.h>
#include <cuda_fp16.h>
#include <cstdint>

// ---------------- problem constants ----------------
#define TT      4096
#define CIN     256
#define COUT    256
#define BBATCH  8
#define SGATE   (BBATCH*COUT*TT)     // 8388608

// GEMM tiling
#define BM      128
#define BN      128
#define BK      64                    // 64-k tiles: 8 tiles, 8 barriers
#define NKT64   8
#define ROWB    128                   // 64 halves, XOR-swizzled chunks (no pad)
#define STAGEB  ((BM+BN)*ROWB)        // 32768 bytes per stage
#define NSTAGE  3
#define GEMM_SMEM (NSTAGE*STAGEB)     // 98304 (same as R11 -> occ 2)

// ---------------- scratch (__device__ globals; alloc-free rule) -------------
__device__ __align__(128) __half2 g_fz[SGATE];                  // (.x=f, .y=i*z) fp16
__device__ __align__(128) __half  g_o [SGATE];                  // o fp16
__device__ __align__(128) __half  xT  [(size_t)BBATCH*TT*CIN];  // [b][t][cin'] perm fp16
__device__ __align__(128) __half  Wp  [8*16*BM*32];             // [y][kt32][m][k'] perm fp16

// ---------------- helpers ----------------
__device__ __forceinline__ float sigm(float v)    { return 1.f / (1.f + __expf(-v)); }
__device__ __forceinline__ float tanh_acc(float v){ return 2.f / (1.f + __expf(-2.f*v)) - 1.f; }
__device__ __forceinline__ uint32_t smem_u32(const void* p) {
    uint32_t a;
    asm("{ .reg .u64 t; cvta.to.shared.u64 t, %1; cvt.u32.u64 %0, t; }" : "=r"(a) : "l"(p));
    return a;
}
// inverse of the frag interleave: dest slot j' (0..15) -> source k-in-16
__device__ __forceinline__ int invp(int jp) {
    int t4 = jp >> 2, pos = jp & 3;
    return 2 * t4 + (pos & 1) + 8 * (pos >> 1);
}

// ---------------------------------------------------------------------------
// Pre-kernel 1: x [b][cin][t] -> xT [b][t][cin'] fp16, k-interleaved per 16
// ---------------------------------------------------------------------------
__global__ __launch_bounds__(256)
void k_xprep(const float* __restrict__ x)
{
    __shared__ float s[32][33];
    const int t0 = blockIdx.x * 32, c0 = blockIdx.y * 32, b = blockIdx.z;
    const int lane = threadIdx.x & 31;

    #pragma unroll
    for (int rr = threadIdx.x >> 5; rr < 32; rr += 8)
        s[rr][lane] = x[((size_t)(b * CIN + c0 + rr)) * TT + t0 + lane];
    __syncthreads();

    #pragma unroll
    for (int i = 0; i < 2; i++) {
        int sl = threadIdx.x + i * 256;       // 512 u32 slots: 32 trow x 16
        int trow = sl >> 4, ms = sl & 15;
        int grp = ms >> 3, jp = (2 * ms) & 15;
        int c0s = grp * 16 + invp(jp);
        int c1s = grp * 16 + invp(jp + 1);
        __half2 v = __floats2half2_rn(s[c0s][trow], s[c1s][trow]);
        ((__half2*)xT)[(((size_t)(b * TT + t0 + trow)) * CIN + c0 >> 1) + ms] = v;
    }
}

// ---------------------------------------------------------------------------
// Pre-kernel 2: W [1024][256][2] -> Wp [y][kt32][m][k'] fp16 (permute+interleave)
// ---------------------------------------------------------------------------
__global__ __launch_bounds__(256)
void k_wprep(const float* __restrict__ W)
{
    const int kt = blockIdx.x, y = blockIdx.y;
    __half2* dst = (__half2*)(Wp + ((size_t)(y * 16 + kt) << 12));
    #pragma unroll
    for (int i = 0; i < 8; i++) {
        int sl = threadIdx.x + i * 256;       // 2048 u32 slots: 128 m x 16
        int m = sl >> 4, ms = sl & 15;
        int grp = ms >> 3, jp = (2 * ms) & 15;
        int wrow = (m >> 5) * 256 + y * 32 + (m & 31);
        int kk0 = kt * 32 + grp * 16 + invp(jp);
        int kk1 = kt * 32 + grp * 16 + invp(jp + 1);
        float v0 = W[wrow * 512 + ((kk0 & 255) << 1) + (kk0 >> 8)];
        float v1 = W[wrow * 512 + ((kk1 & 255) << 1) + (kk1 >> 8)];
        dst[sl] = __floats2half2_rn(v0, v1);
    }
}

// ---------------------------------------------------------------------------
// Kernel 3: fp16 mma.sync GEMM, BK=64 tiles (8 barriers), XOR-swizzled smem,
//   3-stage cp.async pipeline, occ 2. Epilogue unchanged (proven).
// ---------------------------------------------------------------------------
__global__ __launch_bounds__(256, 2)
void qrnn_gemm(const float* __restrict__ bias)
{
    extern __shared__ char smem[];
    __shared__ float bias_s[BM];

    const int tid    = threadIdx.x;
    const int lane   = tid & 31;
    const int wid    = tid >> 5;
    const int warp_m = wid >> 1;         // gate 0:Z 1:F 2:O 3:I
    const int warp_n = wid & 1;
    const int g4     = lane >> 2;
    const int t4     = lane & 3;

    const int y   = blockIdx.y;
    const int oc0 = y * 32;
    const int b   = blockIdx.x >> 5;
    const int t0  = (blockIdx.x & 31) * BN;

    if (tid < BM)
        bias_s[tid] = bias[(tid >> 5) * 256 + oc0 + (tid & 31)];

    float acc[2][8][4];
    #pragma unroll
    for (int im = 0; im < 2; im++)
        #pragma unroll
        for (int in = 0; in < 8; in++)
            #pragma unroll
            for (int ci = 0; ci < 4; ci++) acc[im][in][ci] = 0.f;

    // 2048 16B chunks per tile (A 1024 + B 1024); 8 per thread.
    // Store chunk cu of row r at swizzled chunk (cu ^ ((r&3)<<1)).
    #define PREFETCH(KT, BUF) do {                                              \
        const int kt_ = (KT);                                                   \
        char* stA_ = smem + (BUF) * STAGEB;                                     \
        char* stB_ = stA_ + BM * ROWB;                                          \
        const __half* wc_ = Wp + ((size_t)(y * 16 + 2 * kt_) << 12);            \
        const int tap_  = (kt_ < 4) ? 1 : 0;                                    \
        const int cin0_ = (kt_ & 3) * 64;                                       \
        _Pragma("unroll")                                                       \
        for (int i_ = 0; i_ < 8; i_++) {                                        \
            int u_ = tid + i_ * 256;                                            \
            if (u_ < 1024) {                                                    \
                int r_ = u_ >> 3, cu_ = u_ & 7;                                 \
                int scu_ = cu_ ^ ((r_ & 3) << 1);                               \
                uint32_t da_ = smem_u32(stA_ + r_ * ROWB + scu_ * 16);          \
                const __half* src_ = wc_ + ((cu_ >> 2) << 12) + r_ * 32 + (cu_ & 3) * 8; \
                asm volatile("cp.async.cg.shared.global [%0], [%1], 16;"        \
                    :: "r"(da_), "l"(src_) : "memory");                         \
            } else {                                                            \
                int v_ = u_ - 1024, r_ = v_ >> 3, cu_ = v_ & 7;                 \
                int scu_ = cu_ ^ ((r_ & 3) << 1);                               \
                uint32_t db_ = smem_u32(stB_ + r_ * ROWB + scu_ * 16);          \
                int tg_ = t0 + r_ - tap_;                                       \
                int sz_ = (tg_ >= 0) ? 16 : 0;                                  \
                const __half* src_ = xT + ((size_t)(b * TT + tg_) * CIN + cin0_ + cu_ * 8); \
                asm volatile("cp.async.cg.shared.global [%0], [%1], 16, %2;"    \
                    :: "r"(db_), "l"(src_), "r"(sz_) : "memory");               \
            }                                                                   \
        }                                                                       \
        asm volatile("cp.async.commit_group;" ::: "memory");                    \
    } while (0)

    PREFETCH(0, 0);
    PREFETCH(1, 1);

    #pragma unroll 1
    for (int kt = 0; kt < NKT64; kt++) {
        if (kt == NKT64 - 1) asm volatile("cp.async.wait_group 0;" ::: "memory");
        else                 asm volatile("cp.async.wait_group 1;" ::: "memory");
        __syncthreads();   // stage kt visible; buffer (kt+2)%3 free (compute kt-1 done)
        if (kt + 2 < NKT64) PREFETCH(kt + 2, (kt + 2) % 3);

        const char* As = smem + (kt % 3) * STAGEB;
        const char* Bs = As + BM * ROWB;
        const int row0 = warp_m * 32 + g4;
        const int col0 = warp_n * 64 + g4;
        const int g3   = g4 & 3;
        const int wofs = (t4 >> 1) * 16 + (t4 & 1) * 8;  // within swizzle pair

        #pragma unroll
        for (int s = 0; s < 4; s++) {
            const int kb = ((s ^ g3) << 5) + wofs;   // swizzled byte in 128B row
            uint2 a00 = *(const uint2*)(As + (row0     ) * ROWB + kb);
            uint2 a08 = *(const uint2*)(As + (row0 +  8) * ROWB + kb);
            uint2 a16 = *(const uint2*)(As + (row0 + 16) * ROWB + kb);
            uint2 a24 = *(const uint2*)(As + (row0 + 24) * ROWB + kb);
            uint2 bv[8];
            #pragma unroll
            for (int in = 0; in < 8; in++)
                bv[in] = *(const uint2*)(Bs + (col0 + in * 8) * ROWB + kb);
            #pragma unroll
            for (int in = 0; in < 8; in++) {
                asm volatile(
                    "mma.sync.aligned.m16n8k16.row.col.f32.f16.f16.f32 "
                    "{%0,%1,%2,%3}, {%4,%5,%6,%7}, {%8,%9}, {%0,%1,%2,%3};\n"
                    : "+f"(acc[0][in][0]), "+f"(acc[0][in][1]),
                      "+f"(acc[0][in][2]), "+f"(acc[0][in][3])
                    : "r"(a00.x), "r"(a08.x), "r"(a00.y), "r"(a08.y),
                      "r"(bv[in].x), "r"(bv[in].y));
                asm volatile(
                    "mma.sync.aligned.m16n8k16.row.col.f32.f16.f16.f32 "
                    "{%0,%1,%2,%3}, {%4,%5,%6,%7}, {%8,%9}, {%0,%1,%2,%3};\n"
                    : "+f"(acc[1][in][0]), "+f"(acc[1][in][1]),
                      "+f"(acc[1][in][2]), "+f"(acc[1][in][3])
                    : "r"(a16.x), "r"(a24.x), "r"(a16.y), "r"(a24.y),
                      "r"(bv[in].x), "r"(bv[in].y));
            }
        }
    }
    #undef PREFETCH
    __syncthreads();   // all MMA reads done before smem reuse as staging

    // ---- Epilogue: single round. 4 gate buffers (Z,F,O,I), one barrier. ----
    #define BSTRIDE 132
    {
        float* St = (float*)smem + warp_m * (32 * BSTRIDE);
        #pragma unroll
        for (int im = 0; im < 2; im++)
            #pragma unroll
            for (int in = 0; in < 8; in++)
                #pragma unroll
                for (int ci = 0; ci < 4; ci++) {
                    int r  = im * 16 + g4 + ((ci >> 1) << 3);
                    int cc = warp_n * 64 + in * 8 + (t4 << 1) + (ci & 1);
                    float v = acc[im][in][ci] + bias_s[warp_m * 32 + r];
                    v = (warp_m == 0) ? tanh_acc(v) : sigm(v);
                    St[r * BSTRIDE + cc] = v;
                }
    }
    __syncthreads();
    {
        const float* Sz = (float*)smem;
        const float* Sf = Sz + 32 * BSTRIDE;
        const float* So = Sz + 2 * (32 * BSTRIDE);
        const float* Si = Sz + 3 * (32 * BSTRIDE);
        #pragma unroll
        for (int i = 0; i < 16; i++) {
            int e = tid + i * 256;
            int r = e >> 7, cc = e & 127;
            int sidx = r * BSTRIDE + cc;
            size_t gidx = ((size_t)(b * COUT + oc0 + r)) * TT + t0 + cc;
            g_fz[gidx] = __floats2half2_rn(Sf[sidx], Sz[sidx] * Si[sidx]);
            g_o [gidx] = __float2half_rn(So[sidx]);
        }
    }
    #undef BSTRIDE
}

// ---------------------------------------------------------------------------
// Kernel 4: linear recurrence scan over fp16 packed gates (proven, 18.3us).
//   256 threads/block, 16 elems/thread. c_t = f*c + iz ; H = o*c
// ---------------------------------------------------------------------------
__global__ __launch_bounds__(256)
void qrnn_scan(float* __restrict__ out)
{
    __shared__ float wa[8], wb[8];

    const int tid  = threadIdx.x;
    const int lane = tid & 31;
    const int wrp  = tid >> 5;
    const size_t my = (size_t)blockIdx.x * TT + tid * 16;

    float f[16], z[16];
    #pragma unroll
    for (int q = 0; q < 4; q++) {
        uint4 v = ((const uint4*)(g_fz + my))[q];
        float2 p0 = __half22float2(*(const __half2*)&v.x);
        float2 p1 = __half22float2(*(const __half2*)&v.y);
        float2 p2 = __half22float2(*(const __half2*)&v.z);
        float2 p3 = __half22float2(*(const __half2*)&v.w);
        f[q*4+0] = p0.x; z[q*4+0] = p0.y;
        f[q*4+1] = p1.x; z[q*4+1] = p1.y;
        f[q*4+2] = p2.x; z[q*4+2] = p2.y;
        f[q*4+3] = p3.x; z[q*4+3] = p3.y;
    }

    float a = 1.f, bb = 0.f;
    #pragma unroll
    for (int j = 0; j < 16; j++) { a *= f[j]; bb = f[j] * bb + z[j]; }

    #pragma unroll
    for (int d = 1; d < 32; d <<= 1) {
        float ua = __shfl_up_sync(0xffffffffu, a,  d);
        float ub = __shfl_up_sync(0xffffffffu, bb, d);
        if (lane >= d) { bb = a * ub + bb; a = a * ua; }
    }
    if (lane == 31) { wa[wrp] = a; wb[wrp] = bb; }
    __syncthreads();
    float pb = 0.f;
    #pragma unroll
    for (int w = 0; w < 7; w++)
        if (w < wrp) pb = wa[w] * pb + wb[w];
    float ea = __shfl_up_sync(0xffffffffu, a,  1);
    float eb = __shfl_up_sync(0xffffffffu, bb, 1);
    if (lane == 0) { ea = 1.f; eb = 0.f; }
    float c = ea * pb + eb;              // carry into this chunk (c_init = 0)

    #pragma unroll
    for (int j = 0; j < 16; j++) { c = f[j] * c + z[j]; f[j] = c; }

    uint4 o0 = ((const uint4*)(g_o + my))[0];
    uint4 o1 = ((const uint4*)(g_o + my))[1];
    float ov[16];
    {
        const uint32_t* w0 = (const uint32_t*)&o0;
        const uint32_t* w1 = (const uint32_t*)&o1;
        #pragma unroll
        for (int q = 0; q < 4; q++) {
            float2 p = __half22float2(*(const __half2*)&w0[q]);
            ov[q*2+0] = p.x; ov[q*2+1] = p.y;
        }
        #pragma unroll
        for (int q = 0; q < 4; q++) {
            float2 p = __half22float2(*(const __half2*)&w1[q]);
            ov[8+q*2+0] = p.x; ov[8+q*2+1] = p.y;
        }
    }

    #pragma unroll
    for (int j = 0; j < 4; j++) {
        float4 r;
        r.x = ov[j*4+0] * f[j*4+0]; r.y = ov[j*4+1] * f[j*4+1];
        r.z = ov[j*4+2] * f[j*4+2]; r.w = ov[j*4+3] * f[j*4+3];
        ((float4*)(out + my))[j] = r;
    }
}

extern "C" void kernel_launch(void* const* d_in, const int* in_sizes, int n_in,
                              void* d_out, int out_size)
{
    const float* x    = (const float*)d_in[0];  // [8, 256, 4096]
    const float* W    = (const float*)d_in[1];  // [1024, 256, 2]
    const float* bias = (const float*)d_in[2];  // [1024]
    float* out = (float*)d_out;                 // [8, 256, 4096]

    static int smem_set = 0;
    if (!smem_set) {
        cudaFuncSetAttribute(qrnn_gemm, cudaFuncAttributeMaxDynamicSharedMemorySize, GEMM_SMEM);
        smem_set = 1;
    }

    k_xprep<<<dim3(TT / 32, CIN / 32, BBATCH), 256>>>(x);
    k_wprep<<<dim3(16, 8), 256>>>(W);
    qrnn_gemm<<<dim3(BBATCH * TT / BN, 8), 256, GEMM_SMEM>>>(bias);
    qrnn_scan<<<BBATCH * COUT, 256>>>(out);
}

// round 15
// speedup vs baseline: 1.3993x; 1.0226x over previous
#include <cuda_runtime.h>
#include <cuda_fp16.h>
#include <cstdint>

// ---------------- problem constants ----------------
#define TT      4096
#define CIN     256
#define COUT    256
#define BBATCH  8
#define SGATE   (BBATCH*COUT*TT)     // 8388608

// GEMM tiling
#define BM      128
#define BN      128
#define ROWB    128                   // 64 halves, XOR-swizzled chunks (no pad)
#define STAGEB  ((BM+BN)*ROWB)        // 32768 bytes per stage
#define NTILES  2048                  // 256 nt x 8 y
#define GRID    304                   // 2 x 152 SMs (GB300)
#define SSTRIDE 68                    // staging stride in __half2 (136 halves)
#define STAGING (4*32*SSTRIDE*4)      // 34816 bytes
#define GEMM_SMEM (2*STAGEB + STAGING)  // 100352

// ---------------- scratch (__device__ globals; alloc-free rule) -------------
__device__ __align__(128) __half2 g_fz[SGATE];                  // (.x=f, .y=i*z) fp16
__device__ __align__(128) __half  g_o [SGATE];                  // o fp16
__device__ __align__(128) __half  xT  [(size_t)BBATCH*TT*CIN];  // [b][t][cin'] perm fp16
__device__ __align__(128) __half  Wp  [8*16*BM*32];             // [y][kt32][m][k'] perm fp16

// ---------------- helpers ----------------
__device__ __forceinline__ float sigm(float v)    { return 1.f / (1.f + __expf(-v)); }
__device__ __forceinline__ float tanh_acc(float v){ return 2.f / (1.f + __expf(-2.f*v)) - 1.f; }
__device__ __forceinline__ uint32_t smem_u32(const void* p) {
    uint32_t a;
    asm("{ .reg .u64 t; cvta.to.shared.u64 t, %1; cvt.u32.u64 %0, t; }" : "=r"(a) : "l"(p));
    return a;
}
// inverse of the frag interleave: dest slot j' (0..15) -> source k-in-16
__device__ __forceinline__ int invp(int jp) {
    int t4 = jp >> 2, pos = jp & 3;
    return 2 * t4 + (pos & 1) + 8 * (pos >> 1);
}

// ---------------------------------------------------------------------------
// Pre-kernel 1: x [b][cin][t] -> xT [b][t][cin'] fp16, k-interleaved per 16
// ---------------------------------------------------------------------------
__global__ __launch_bounds__(256)
void k_xprep(const float* __restrict__ x)
{
    __shared__ float s[32][33];
    const int t0 = blockIdx.x * 32, c0 = blockIdx.y * 32, b = blockIdx.z;
    const int lane = threadIdx.x & 31;

    #pragma unroll
    for (int rr = threadIdx.x >> 5; rr < 32; rr += 8)
        s[rr][lane] = x[((size_t)(b * CIN + c0 + rr)) * TT + t0 + lane];
    __syncthreads();

    #pragma unroll
    for (int i = 0; i < 2; i++) {
        int sl = threadIdx.x + i * 256;       // 512 u32 slots: 32 trow x 16
        int trow = sl >> 4, ms = sl & 15;
        int grp = ms >> 3, jp = (2 * ms) & 15;
        int c0s = grp * 16 + invp(jp);
        int c1s = grp * 16 + invp(jp + 1);
        __half2 v = __floats2half2_rn(s[c0s][trow], s[c1s][trow]);
        ((__half2*)xT)[(((size_t)(b * TT + t0 + trow)) * CIN + c0 >> 1) + ms] = v;
    }
}

// ---------------------------------------------------------------------------
// Pre-kernel 2: W [1024][256][2] -> Wp [y][kt32][m][k'] fp16 (permute+interleave)
// ---------------------------------------------------------------------------
__global__ __launch_bounds__(256)
void k_wprep(const float* __restrict__ W)
{
    const int kt = blockIdx.x, y = blockIdx.y;
    __half2* dst = (__half2*)(Wp + ((size_t)(y * 16 + kt) << 12));
    #pragma unroll
    for (int i = 0; i < 8; i++) {
        int sl = threadIdx.x + i * 256;       // 2048 u32 slots: 128 m x 16
        int m = sl >> 4, ms = sl & 15;
        int grp = ms >> 3, jp = (2 * ms) & 15;
        int wrow = (m >> 5) * 256 + y * 32 + (m & 31);
        int kk0 = kt * 32 + grp * 16 + invp(jp);
        int kk1 = kt * 32 + grp * 16 + invp(jp + 1);
        float v0 = W[wrow * 512 + ((kk0 & 255) << 1) + (kk0 >> 8)];
        float v1 = W[wrow * 512 + ((kk1 & 255) << 1) + (kk1 >> 8)];
        dst[sl] = __floats2half2_rn(v0, v1);
    }
}

// ---------------------------------------------------------------------------
// Kernel 3: PERSISTENT fp16 mma.sync GEMM. 304 CTAs, ~7 tiles each, continuous
//   2-stage cp.async pipeline across tiles; epilogue overlaps next-tile load
//   via a dedicated fp16 staging region.
// ---------------------------------------------------------------------------
__global__ __launch_bounds__(256, 2)
void qrnn_gemm(const float* __restrict__ bias)
{
    extern __shared__ char smem[];
    __shared__ float bias_s[BM];

    const int tid    = threadIdx.x;
    const int lane   = tid & 31;
    const int wid    = tid >> 5;
    const int warp_m = wid >> 1;         // gate 0:Z 1:F 2:O 3:I
    const int warp_n = wid & 1;
    const int g4     = lane >> 2;
    const int t4     = lane & 3;
    const int cta    = blockIdx.x;

    // PREFETCH for global chunk Q (chunk = tile-local k64 index, 8 per tile).
    // tile = cta + (Q>>3)*GRID ; kt = Q&7 ; buffer = Q&1.
    #define PREFETCH(Q) do {                                                    \
        const int q_ = (Q);                                                     \
        const int tile_ = cta + (q_ >> 3) * GRID;                               \
        const int kt_ = q_ & 7;                                                 \
        const int y_ = tile_ & 7;                                               \
        const int nt_ = tile_ >> 3;                                             \
        const int b_ = nt_ >> 5;                                                \
        const int t0_ = (nt_ & 31) * BN;                                        \
        char* stA_ = smem + (q_ & 1) * STAGEB;                                  \
        char* stB_ = stA_ + BM * ROWB;                                          \
        const __half* wc_ = Wp + ((size_t)(y_ * 16 + 2 * kt_) << 12);           \
        const int tap_  = (kt_ < 4) ? 1 : 0;                                    \
        const int cin0_ = (kt_ & 3) * 64;                                       \
        _Pragma("unroll")                                                       \
        for (int i_ = 0; i_ < 8; i_++) {                                        \
            int u_ = tid + i_ * 256;                                            \
            if (u_ < 1024) {                                                    \
                int r_ = u_ >> 3, cu_ = u_ & 7;                                 \
                int scu_ = cu_ ^ ((r_ & 3) << 1);                               \
                uint32_t da_ = smem_u32(stA_ + r_ * ROWB + scu_ * 16);          \
                const __half* src_ = wc_ + ((cu_ >> 2) << 12) + r_ * 32 + (cu_ & 3) * 8; \
                asm volatile("cp.async.cg.shared.global [%0], [%1], 16;"        \
                    :: "r"(da_), "l"(src_) : "memory");                         \
            } else {                                                            \
                int v_ = u_ - 1024, r_ = v_ >> 3, cu_ = v_ & 7;                 \
                int scu_ = cu_ ^ ((r_ & 3) << 1);                               \
                uint32_t db_ = smem_u32(stB_ + r_ * ROWB + scu_ * 16);          \
                int tg_ = t0_ + r_ - tap_;                                      \
                int sz_ = (tg_ >= 0) ? 16 : 0;                                  \
                const __half* src_ = xT + ((size_t)(b_ * TT + tg_) * CIN + cin0_ + cu_ * 8); \
                asm volatile("cp.async.cg.shared.global [%0], [%1], 16, %2;"    \
                    :: "r"(db_), "l"(src_), "r"(sz_) : "memory");               \
            }                                                                   \
        }                                                                       \
        asm volatile("cp.async.commit_group;" ::: "memory");                    \
    } while (0)

    int q = 0;                          // global chunk counter for this CTA
    PREFETCH(0);

    #pragma unroll 1
    for (int tile = cta; tile < NTILES; tile += GRID) {
        const int y   = tile & 7;
        const int nt  = tile >> 3;
        const int b   = nt >> 5;
        const int t0  = (nt & 31) * BN;
        const int oc0 = y * 32;

        if (tid < BM)
            bias_s[tid] = bias[(tid >> 5) * 256 + oc0 + (tid & 31)];

        float acc[2][8][4];
        #pragma unroll
        for (int im = 0; im < 2; im++)
            #pragma unroll
            for (int in = 0; in < 8; in++)
                #pragma unroll
                for (int ci = 0; ci < 4; ci++) acc[im][in][ci] = 0.f;

        #pragma unroll 1
        for (int kt = 0; kt < 8; kt++, q++) {
            asm volatile("cp.async.wait_group 0;" ::: "memory");
            __syncthreads();            // chunk q visible; other buffer free
            const bool more = (kt < 7) || (tile + GRID < NTILES);
            if (more) PREFETCH(q + 1);  // next chunk (possibly next tile)

            const char* As = smem + (q & 1) * STAGEB;
            const char* Bs = As + BM * ROWB;
            const int row0 = warp_m * 32 + g4;
            const int col0 = warp_n * 64 + g4;
            const int g3   = g4 & 3;
            const int wofs = (t4 >> 1) * 16 + (t4 & 1) * 8;

            #pragma unroll
            for (int s = 0; s < 4; s++) {
                const int kb = ((s ^ g3) << 5) + wofs;
                uint2 a00 = *(const uint2*)(As + (row0     ) * ROWB + kb);
                uint2 a08 = *(const uint2*)(As + (row0 +  8) * ROWB + kb);
                uint2 a16 = *(const uint2*)(As + (row0 + 16) * ROWB + kb);
                uint2 a24 = *(const uint2*)(As + (row0 + 24) * ROWB + kb);
                uint2 bv[8];
                #pragma unroll
                for (int in = 0; in < 8; in++)
                    bv[in] = *(const uint2*)(Bs + (col0 + in * 8) * ROWB + kb);
                #pragma unroll
                for (int in = 0; in < 8; in++) {
                    asm volatile(
                        "mma.sync.aligned.m16n8k16.row.col.f32.f16.f16.f32 "
                        "{%0,%1,%2,%3}, {%4,%5,%6,%7}, {%8,%9}, {%0,%1,%2,%3};\n"
                        : "+f"(acc[0][in][0]), "+f"(acc[0][in][1]),
                          "+f"(acc[0][in][2]), "+f"(acc[0][in][3])
                        : "r"(a00.x), "r"(a08.x), "r"(a00.y), "r"(a08.y),
                          "r"(bv[in].x), "r"(bv[in].y));
                    asm volatile(
                        "mma.sync.aligned.m16n8k16.row.col.f32.f16.f16.f32 "
                        "{%0,%1,%2,%3}, {%4,%5,%6,%7}, {%8,%9}, {%0,%1,%2,%3};\n"
                        : "+f"(acc[1][in][0]), "+f"(acc[1][in][1]),
                          "+f"(acc[1][in][2]), "+f"(acc[1][in][3])
                        : "r"(a16.x), "r"(a24.x), "r"(a16.y), "r"(a24.y),
                          "r"(bv[in].x), "r"(bv[in].y));
                }
            }
        }

        // ---- Epilogue in dedicated fp16 staging; overlaps in-flight prefetch ----
        {
            __half2* St = (__half2*)(smem + 2 * STAGEB) + warp_m * (32 * SSTRIDE);
            #pragma unroll
            for (int im = 0; im < 2; im++)
                #pragma unroll
                for (int in = 0; in < 8; in++)
                    #pragma unroll
                    for (int cp = 0; cp < 2; cp++) {
                        int r  = im * 16 + g4 + cp * 8;
                        int cu = warp_n * 32 + in * 4 + t4;
                        float bv = bias_s[warp_m * 32 + r];
                        float v0 = acc[im][in][cp * 2 + 0] + bv;
                        float v1 = acc[im][in][cp * 2 + 1] + bv;
                        if (warp_m == 0) { v0 = tanh_acc(v0); v1 = tanh_acc(v1); }
                        else             { v0 = sigm(v0);     v1 = sigm(v1);     }
                        St[r * SSTRIDE + cu] = __floats2half2_rn(v0, v1);
                    }
        }
        __syncthreads();
        {
            const __half2* Sz = (__half2*)(smem + 2 * STAGEB);
            const __half2* Sf = Sz + 32 * SSTRIDE;
            const __half2* So = Sf + 32 * SSTRIDE;
            const __half2* Si = So + 32 * SSTRIDE;
            #pragma unroll
            for (int i = 0; i < 8; i++) {
                int e = tid + i * 256;         // 2048 = 32 rows x 64 col-pairs
                int r = e >> 6, cu = e & 63;
                float2 zf = __half22float2(Sz[r * SSTRIDE + cu]);
                float2 ff = __half22float2(Sf[r * SSTRIDE + cu]);
                float2 of = __half22float2(So[r * SSTRIDE + cu]);
                float2 ii = __half22float2(Si[r * SSTRIDE + cu]);
                size_t gb = ((size_t)(b * COUT + oc0 + r)) * TT + t0 + cu * 2;
                g_fz[gb + 0] = __floats2half2_rn(ff.x, zf.x * ii.x);
                g_fz[gb + 1] = __floats2half2_rn(ff.y, zf.y * ii.y);
                *(__half2*)(g_o + gb) = __floats2half2_rn(of.x, of.y);
            }
        }
        // next tile's first chunk sync doubles as the closing barrier
    }
    #undef PREFETCH
}

// ---------------------------------------------------------------------------
// Kernel 4: linear recurrence scan over fp16 packed gates (proven, 18.1us).
//   256 threads/block, 16 elems/thread. c_t = f*c + iz ; H = o*c
// ---------------------------------------------------------------------------
__global__ __launch_bounds__(256)
void qrnn_scan(float* __restrict__ out)
{
    __shared__ float wa[8], wb[8];

    const int tid  = threadIdx.x;
    const int lane = tid & 31;
    const int wrp  = tid >> 5;
    const size_t my = (size_t)blockIdx.x * TT + tid * 16;

    float f[16], z[16];
    #pragma unroll
    for (int q = 0; q < 4; q++) {
        uint4 v = ((const uint4*)(g_fz + my))[q];
        float2 p0 = __half22float2(*(const __half2*)&v.x);
        float2 p1 = __half22float2(*(const __half2*)&v.y);
        float2 p2 = __half22float2(*(const __half2*)&v.z);
        float2 p3 = __half22float2(*(const __half2*)&v.w);
        f[q*4+0] = p0.x; z[q*4+0] = p0.y;
        f[q*4+1] = p1.x; z[q*4+1] = p1.y;
        f[q*4+2] = p2.x; z[q*4+2] = p2.y;
        f[q*4+3] = p3.x; z[q*4+3] = p3.y;
    }

    float a = 1.f, bb = 0.f;
    #pragma unroll
    for (int j = 0; j < 16; j++) { a *= f[j]; bb = f[j] * bb + z[j]; }

    #pragma unroll
    for (int d = 1; d < 32; d <<= 1) {
        float ua = __shfl_up_sync(0xffffffffu, a,  d);
        float ub = __shfl_up_sync(0xffffffffu, bb, d);
        if (lane >= d) { bb = a * ub + bb; a = a * ua; }
    }
    if (lane == 31) { wa[wrp] = a; wb[wrp] = bb; }
    __syncthreads();
    float pb = 0.f;
    #pragma unroll
    for (int w = 0; w < 7; w++)
        if (w < wrp) pb = wa[w] * pb + wb[w];
    float ea = __shfl_up_sync(0xffffffffu, a,  1);
    float eb = __shfl_up_sync(0xffffffffu, bb, 1);
    if (lane == 0) { ea = 1.f; eb = 0.f; }
    float c = ea * pb + eb;              // carry into this chunk (c_init = 0)

    #pragma unroll
    for (int j = 0; j < 16; j++) { c = f[j] * c + z[j]; f[j] = c; }

    uint4 o0 = ((const uint4*)(g_o + my))[0];
    uint4 o1 = ((const uint4*)(g_o + my))[1];
    float ov[16];
    {
        const uint32_t* w0 = (const uint32_t*)&o0;
        const uint32_t* w1 = (const uint32_t*)&o1;
        #pragma unroll
        for (int q = 0; q < 4; q++) {
            float2 p = __half22float2(*(const __half2*)&w0[q]);
            ov[q*2+0] = p.x; ov[q*2+1] = p.y;
        }
        #pragma unroll
        for (int q = 0; q < 4; q++) {
            float2 p = __half22float2(*(const __half2*)&w1[q]);
            ov[8+q*2+0] = p.x; ov[8+q*2+1] = p.y;
        }
    }

    #pragma unroll
    for (int j = 0; j < 4; j++) {
        float4 r;
        r.x = ov[j*4+0] * f[j*4+0]; r.y = ov[j*4+1] * f[j*4+1];
        r.z = ov[j*4+2] * f[j*4+2]; r.w = ov[j*4+3] * f[j*4+3];
        ((float4*)(out + my))[j] = r;
    }
}

extern "C" void kernel_launch(void* const* d_in, const int* in_sizes, int n_in,
                              void* d_out, int out_size)
{
    const float* x    = (const float*)d_in[0];  // [8, 256, 4096]
    const float* W    = (const float*)d_in[1];  // [1024, 256, 2]
    const float* bias = (const float*)d_in[2];  // [1024]
    float* out = (float*)d_out;                 // [8, 256, 4096]

    static int smem_set = 0;
    if (!smem_set) {
        cudaFuncSetAttribute(qrnn_gemm, cudaFuncAttributeMaxDynamicSharedMemorySize, GEMM_SMEM);
        smem_set = 1;
    }

    k_xprep<<<dim3(TT / 32, CIN / 32, BBATCH), 256>>>(x);
    k_wprep<<<dim3(16, 8), 256>>>(W);
    qrnn_gemm<<<GRID, 256, GEMM_SMEM>>>(bias);
    qrnn_scan<<<BBATCH * COUT, 256>>>(out);
}

// round 16
// speedup vs baseline: 1.4667x; 1.0482x over previous
#include <cuda_runtime.h>
#include <cuda_fp16.h>
#include <cstdint>

// ---------------- problem constants ----------------
#define TT      4096
#define CIN     256
#define COUT    256
#define BBATCH  8
#define SGATE   (BBATCH*COUT*TT)     // 8388608

// GEMM tiling
#define BM      128
#define BN      128
#define ROWB    128                   // 64 halves, XOR-swizzled chunks (no pad)
#define STAGEB  ((BM+BN)*ROWB)        // 32768 bytes per stage
#define NTILES  2048                  // 256 nt x 8 y
#define GRID    304                   // 2 x 152 SMs (GB300)
#define SST     132                   // staging stride (elements)
#define STG_FZ  (2*STAGEB)            // __half2[32*SST] = 16896 B
#define STG_O   (STG_FZ + 32*SST*4)   // __half [32*SST] = 8448 B
#define GEMM_SMEM (STG_O + 32*SST*2 - 0)  // 90880

// ---------------- scratch (__device__ globals; alloc-free rule) -------------
__device__ __align__(128) __half2 g_fz[SGATE];                  // (.x=f, .y=i*z) fp16
__device__ __align__(128) __half  g_o [SGATE];                  // o fp16
__device__ __align__(128) __half  xT  [(size_t)BBATCH*TT*CIN];  // [b][t][cin'] perm fp16
__device__ __align__(128) __half  Wp  [8*16*BM*32];             // [y][kt32][m][k'] perm fp16

// ---------------- helpers ----------------
__device__ __forceinline__ float sigm(float v)    { return 1.f / (1.f + __expf(-v)); }
__device__ __forceinline__ float tanh_acc(float v){ return 2.f / (1.f + __expf(-2.f*v)) - 1.f; }
__device__ __forceinline__ uint32_t smem_u32(const void* p) {
    uint32_t a;
    asm("{ .reg .u64 t; cvta.to.shared.u64 t, %1; cvt.u32.u64 %0, t; }" : "=r"(a) : "l"(p));
    return a;
}
// inverse of the frag interleave: dest slot j' (0..15) -> source k-in-16
__device__ __forceinline__ int invp(int jp) {
    int t4 = jp >> 2, pos = jp & 3;
    return 2 * t4 + (pos & 1) + 8 * (pos >> 1);
}

// ---------------------------------------------------------------------------
// Pre-kernel 1: x [b][cin][t] -> xT [b][t][cin'] fp16, k-interleaved per 16
// ---------------------------------------------------------------------------
__global__ __launch_bounds__(256)
void k_xprep(const float* __restrict__ x)
{
    __shared__ float s[32][33];
    const int t0 = blockIdx.x * 32, c0 = blockIdx.y * 32, b = blockIdx.z;
    const int lane = threadIdx.x & 31;

    #pragma unroll
    for (int rr = threadIdx.x >> 5; rr < 32; rr += 8)
        s[rr][lane] = x[((size_t)(b * CIN + c0 + rr)) * TT + t0 + lane];
    __syncthreads();

    #pragma unroll
    for (int i = 0; i < 2; i++) {
        int sl = threadIdx.x + i * 256;       // 512 u32 slots: 32 trow x 16
        int trow = sl >> 4, ms = sl & 15;
        int grp = ms >> 3, jp = (2 * ms) & 15;
        int c0s = grp * 16 + invp(jp);
        int c1s = grp * 16 + invp(jp + 1);
        __half2 v = __floats2half2_rn(s[c0s][trow], s[c1s][trow]);
        ((__half2*)xT)[(((size_t)(b * TT + t0 + trow)) * CIN + c0 >> 1) + ms] = v;
    }
}

// ---------------------------------------------------------------------------
// Pre-kernel 2: W -> Wp with GATE-INTERLEAVED rows: within each warp 32-row
//   block, row = gate*8 + oc3, so one thread's D-fragment rows r/r+8/r+16/r+24
//   hold Z/F/O/I for the same output channel.
// ---------------------------------------------------------------------------
__global__ __launch_bounds__(256)
void k_wprep(const float* __restrict__ W)
{
    const int kt = blockIdx.x, y = blockIdx.y;
    __half2* dst = (__half2*)(Wp + ((size_t)(y * 16 + kt) << 12));
    #pragma unroll
    for (int i = 0; i < 8; i++) {
        int sl = threadIdx.x + i * 256;       // 2048 u32 slots: 128 m x 16
        int m = sl >> 4, ms = sl & 15;
        int grp = ms >> 3, jp = (2 * ms) & 15;
        int wm = m >> 5, lr = m & 31;
        int gate = lr >> 3, oc3 = lr & 7;
        int wrow = gate * 256 + y * 32 + wm * 8 + oc3;
        int kk0 = kt * 32 + grp * 16 + invp(jp);
        int kk1 = kt * 32 + grp * 16 + invp(jp + 1);
        float v0 = W[wrow * 512 + ((kk0 & 255) << 1) + (kk0 >> 8)];
        float v1 = W[wrow * 512 + ((kk1 & 255) << 1) + (kk1 >> 8)];
        dst[sl] = __floats2half2_rn(v0, v1);
    }
}

// ---------------------------------------------------------------------------
// Kernel 3: PERSISTENT fp16 mma.sync GEMM, register-local gate combine.
//   304 CTAs; continuous 2-stage cp.async pipeline; 1-sync packed epilogue.
// ---------------------------------------------------------------------------
__global__ __launch_bounds__(256, 2)
void qrnn_gemm(const float* __restrict__ bias)
{
    extern __shared__ char smem[];

    const int tid    = threadIdx.x;
    const int lane   = tid & 31;
    const int wid    = tid >> 5;
    const int warp_m = wid >> 1;
    const int warp_n = wid & 1;
    const int g4     = lane >> 2;
    const int t4     = lane & 3;
    const int cta    = blockIdx.x;
    const int oc_l   = warp_m * 8 + g4;   // tile-local output channel (0..31)

    #define PREFETCH(Q) do {                                                    \
        const int q_ = (Q);                                                     \
        const int tile_ = cta + (q_ >> 3) * GRID;                               \
        const int kt_ = q_ & 7;                                                 \
        const int y_ = tile_ & 7;                                               \
        const int nt_ = tile_ >> 3;                                             \
        const int b_ = nt_ >> 5;                                                \
        const int t0_ = (nt_ & 31) * BN;                                        \
        char* stA_ = smem + (q_ & 1) * STAGEB;                                  \
        char* stB_ = stA_ + BM * ROWB;                                          \
        const __half* wc_ = Wp + ((size_t)(y_ * 16 + 2 * kt_) << 12);           \
        const int tap_  = (kt_ < 4) ? 1 : 0;                                    \
        const int cin0_ = (kt_ & 3) * 64;                                       \
        _Pragma("unroll")                                                       \
        for (int i_ = 0; i_ < 8; i_++) {                                        \
            int u_ = tid + i_ * 256;                                            \
            if (u_ < 1024) {                                                    \
                int r_ = u_ >> 3, cu_ = u_ & 7;                                 \
                int scu_ = cu_ ^ ((r_ & 3) << 1);                               \
                uint32_t da_ = smem_u32(stA_ + r_ * ROWB + scu_ * 16);          \
                const __half* src_ = wc_ + ((cu_ >> 2) << 12) + r_ * 32 + (cu_ & 3) * 8; \
                asm volatile("cp.async.cg.shared.global [%0], [%1], 16;"        \
                    :: "r"(da_), "l"(src_) : "memory");                         \
            } else {                                                            \
                int v_ = u_ - 1024, r_ = v_ >> 3, cu_ = v_ & 7;                 \
                int scu_ = cu_ ^ ((r_ & 3) << 1);                               \
                uint32_t db_ = smem_u32(stB_ + r_ * ROWB + scu_ * 16);          \
                int tg_ = t0_ + r_ - tap_;                                      \
                int sz_ = (tg_ >= 0) ? 16 : 0;                                  \
                const __half* src_ = xT + ((size_t)(b_ * TT + tg_) * CIN + cin0_ + cu_ * 8); \
                asm volatile("cp.async.cg.shared.global [%0], [%1], 16, %2;"    \
                    :: "r"(db_), "l"(src_), "r"(sz_) : "memory");               \
            }                                                                   \
        }                                                                       \
        asm volatile("cp.async.commit_group;" ::: "memory");                    \
    } while (0)

    int q = 0;
    PREFETCH(0);

    #pragma unroll 1
    for (int tile = cta; tile < NTILES; tile += GRID) {
        const int y   = tile & 7;
        const int nt  = tile >> 3;
        const int b   = nt >> 5;
        const int t0  = (nt & 31) * BN;
        const int oc  = y * 32 + oc_l;

        // per-thread bias for all 4 gates of this thread's channel
        const float bz = bias[      oc];
        const float bf = bias[256 + oc];
        const float bo = bias[512 + oc];
        const float bi = bias[768 + oc];

        float acc[2][8][4];
        #pragma unroll
        for (int im = 0; im < 2; im++)
            #pragma unroll
            for (int in = 0; in < 8; in++)
                #pragma unroll
                for (int ci = 0; ci < 4; ci++) acc[im][in][ci] = 0.f;

        #pragma unroll 1
        for (int kt = 0; kt < 8; kt++, q++) {
            asm volatile("cp.async.wait_group 0;" ::: "memory");
            __syncthreads();
            const bool more = (kt < 7) || (tile + GRID < NTILES);
            if (more) PREFETCH(q + 1);

            const char* As = smem + (q & 1) * STAGEB;
            const char* Bs = As + BM * ROWB;
            const int row0 = warp_m * 32 + g4;
            const int col0 = warp_n * 64 + g4;
            const int g3   = g4 & 3;
            const int wofs = (t4 >> 1) * 16 + (t4 & 1) * 8;

            #pragma unroll
            for (int s = 0; s < 4; s++) {
                const int kb = ((s ^ g3) << 5) + wofs;
                uint2 a00 = *(const uint2*)(As + (row0     ) * ROWB + kb);
                uint2 a08 = *(const uint2*)(As + (row0 +  8) * ROWB + kb);
                uint2 a16 = *(const uint2*)(As + (row0 + 16) * ROWB + kb);
                uint2 a24 = *(const uint2*)(As + (row0 + 24) * ROWB + kb);
                uint2 bv[8];
                #pragma unroll
                for (int in = 0; in < 8; in++)
                    bv[in] = *(const uint2*)(Bs + (col0 + in * 8) * ROWB + kb);
                #pragma unroll
                for (int in = 0; in < 8; in++) {
                    asm volatile(
                        "mma.sync.aligned.m16n8k16.row.col.f32.f16.f16.f32 "
                        "{%0,%1,%2,%3}, {%4,%5,%6,%7}, {%8,%9}, {%0,%1,%2,%3};\n"
                        : "+f"(acc[0][in][0]), "+f"(acc[0][in][1]),
                          "+f"(acc[0][in][2]), "+f"(acc[0][in][3])
                        : "r"(a00.x), "r"(a08.x), "r"(a00.y), "r"(a08.y),
                          "r"(bv[in].x), "r"(bv[in].y));
                    asm volatile(
                        "mma.sync.aligned.m16n8k16.row.col.f32.f16.f16.f32 "
                        "{%0,%1,%2,%3}, {%4,%5,%6,%7}, {%8,%9}, {%0,%1,%2,%3};\n"
                        : "+f"(acc[1][in][0]), "+f"(acc[1][in][1]),
                          "+f"(acc[1][in][2]), "+f"(acc[1][in][3])
                        : "r"(a16.x), "r"(a24.x), "r"(a16.y), "r"(a24.y),
                          "r"(bv[in].x), "r"(bv[in].y));
                }
            }
        }

        // ---- Epilogue: register-local combine, packed fp16 staging, 1 sync ----
        {
            __half2* Sfz = (__half2*)(smem + STG_FZ);
            __half*  So  = (__half*) (smem + STG_O);
            #pragma unroll
            for (int in = 0; in < 8; in++)
                #pragma unroll
                for (int p = 0; p < 2; p++) {
                    float z = tanh_acc(acc[0][in][p    ] + bz);
                    float f = sigm    (acc[0][in][2 + p] + bf);
                    float o = sigm    (acc[1][in][p    ] + bo);
                    float i = sigm    (acc[1][in][2 + p] + bi);
                    int c = warp_n * 64 + in * 8 + (t4 << 1) + p;
                    Sfz[oc_l * SST + c] = __floats2half2_rn(f, z * i);
                    So [oc_l * SST + c] = __float2half_rn(o);
                }
        }
        __syncthreads();
        {
            const __half2* Sfz = (const __half2*)(smem + STG_FZ);
            const __half*  So  = (const __half*) (smem + STG_O);
            #pragma unroll
            for (int i = 0; i < 16; i++) {
                int e = tid + i * 256;           // 4096 = 32 rows x 128 cols
                int r = e >> 7, cc = e & 127;
                g_fz[((size_t)(b * COUT + y * 32 + r)) * TT + t0 + cc] =
                    Sfz[r * SST + cc];
            }
            #pragma unroll
            for (int i = 0; i < 8; i++) {
                int e = tid + i * 256;           // 2048 = 32 rows x 64 pairs
                int r = e >> 6, cu = e & 63;
                *(__half2*)(g_o + ((size_t)(b * COUT + y * 32 + r)) * TT + t0 + cu * 2) =
                    *(const __half2*)(So + r * SST + cu * 2);
            }
        }
        // next tile's first-chunk sync doubles as the closing barrier
    }
    #undef PREFETCH
}

// ---------------------------------------------------------------------------
// Kernel 4: linear recurrence scan over fp16 packed gates (proven, 18.0us).
// ---------------------------------------------------------------------------
__global__ __launch_bounds__(256)
void qrnn_scan(float* __restrict__ out)
{
    __shared__ float wa[8], wb[8];

    const int tid  = threadIdx.x;
    const int lane = tid & 31;
    const int wrp  = tid >> 5;
    const size_t my = (size_t)blockIdx.x * TT + tid * 16;

    float f[16], z[16];
    #pragma unroll
    for (int q = 0; q < 4; q++) {
        uint4 v = ((const uint4*)(g_fz + my))[q];
        float2 p0 = __half22float2(*(const __half2*)&v.x);
        float2 p1 = __half22float2(*(const __half2*)&v.y);
        float2 p2 = __half22float2(*(const __half2*)&v.z);
        float2 p3 = __half22float2(*(const __half2*)&v.w);
        f[q*4+0] = p0.x; z[q*4+0] = p0.y;
        f[q*4+1] = p1.x; z[q*4+1] = p1.y;
        f[q*4+2] = p2.x; z[q*4+2] = p2.y;
        f[q*4+3] = p3.x; z[q*4+3] = p3.y;
    }

    float a = 1.f, bb = 0.f;
    #pragma unroll
    for (int j = 0; j < 16; j++) { a *= f[j]; bb = f[j] * bb + z[j]; }

    #pragma unroll
    for (int d = 1; d < 32; d <<= 1) {
        float ua = __shfl_up_sync(0xffffffffu, a,  d);
        float ub = __shfl_up_sync(0xffffffffu, bb, d);
        if (lane >= d) { bb = a * ub + bb; a = a * ua; }
    }
    if (lane == 31) { wa[wrp] = a; wb[wrp] = bb; }
    __syncthreads();
    float pb = 0.f;
    #pragma unroll
    for (int w = 0; w < 7; w++)
        if (w < wrp) pb = wa[w] * pb + wb[w];
    float ea = __shfl_up_sync(0xffffffffu, a,  1);
    float eb = __shfl_up_sync(0xffffffffu, bb, 1);
    if (lane == 0) { ea = 1.f; eb = 0.f; }
    float c = ea * pb + eb;              // carry into this chunk (c_init = 0)

    #pragma unroll
    for (int j = 0; j < 16; j++) { c = f[j] * c + z[j]; f[j] = c; }

    uint4 o0 = ((const uint4*)(g_o + my))[0];
    uint4 o1 = ((const uint4*)(g_o + my))[1];
    float ov[16];
    {
        const uint32_t* w0 = (const uint32_t*)&o0;
        const uint32_t* w1 = (const uint32_t*)&o1;
        #pragma unroll
        for (int q = 0; q < 4; q++) {
            float2 p = __half22float2(*(const __half2*)&w0[q]);
            ov[q*2+0] = p.x; ov[q*2+1] = p.y;
        }
        #pragma unroll
        for (int q = 0; q < 4; q++) {
            float2 p = __half22float2(*(const __half2*)&w1[q]);
            ov[8+q*2+0] = p.x; ov[8+q*2+1] = p.y;
        }
    }

    #pragma unroll
    for (int j = 0; j < 4; j++) {
        float4 r;
        r.x = ov[j*4+0] * f[j*4+0]; r.y = ov[j*4+1] * f[j*4+1];
        r.z = ov[j*4+2] * f[j*4+2]; r.w = ov[j*4+3] * f[j*4+3];
        ((float4*)(out + my))[j] = r;
    }
}

extern "C" void kernel_launch(void* const* d_in, const int* in_sizes, int n_in,
                              void* d_out, int out_size)
{
    const float* x    = (const float*)d_in[0];  // [8, 256, 4096]
    const float* W    = (const float*)d_in[1];  // [1024, 256, 2]
    const float* bias = (const float*)d_in[2];  // [1024]
    float* out = (float*)d_out;                 // [8, 256, 4096]

    static int smem_set = 0;
    if (!smem_set) {
        cudaFuncSetAttribute(qrnn_gemm, cudaFuncAttributeMaxDynamicSharedMemorySize, GEMM_SMEM);
        smem_set = 1;
    }

    k_xprep<<<dim3(TT / 32, CIN / 32, BBATCH), 256>>>(x);
    k_wprep<<<dim3(16, 8), 256>>>(W);
    qrnn_gemm<<<GRID, 256, GEMM_SMEM>>>(bias);
    qrnn_scan<<<BBATCH * COUT, 256>>>(out);
}

// round 17
// speedup vs baseline: 1.4839x; 1.0117x over previous
#include <cuda_runtime.h>
#include <cuda_fp16.h>
#include <cstdint>

// ---------------- problem constants ----------------
#define TT      4096
#define CIN     256
#define COUT    256
#define BBATCH  8
#define SGATE   (BBATCH*COUT*TT)     // 8388608

// GEMM tiling
#define BM      128
#define BN      128
#define ROWB    128                   // 64 halves, XOR-swizzled chunks (no pad)
#define STAGEB  ((BM+BN)*ROWB)        // 32768 bytes per stage
#define NTILES  2048                  // 256 nt x 8 y
#define GRID    304                   // 2 x 152 SMs (GB300)
#define SST     132                   // staging stride (elements)
#define STG_FZ  (2*STAGEB)            // __half2[32*SST] = 16896 B
#define STG_O   (STG_FZ + 32*SST*4)   // __half [32*SST] = 8448 B
#define GEMM_SMEM (STG_O + 32*SST*2)  // 90880

// ---------------- scratch (__device__ globals; alloc-free rule) -------------
__device__ __align__(128) __half2 g_fz[SGATE];                  // (.x=f, .y=i*z) fp16
__device__ __align__(128) __half  g_o [SGATE];                  // o fp16
__device__ __align__(128) __half  xT  [(size_t)BBATCH*TT*CIN];  // [b][t][cin'] perm fp16
__device__ __align__(128) __half  Wp  [8*16*BM*32];             // [y][kt32][m][k'] perm fp16

// ---------------- helpers ----------------
__device__ __forceinline__ float sigm(float v)    { return 1.f / (1.f + __expf(-v)); }
__device__ __forceinline__ float tanh_acc(float v){ return 2.f / (1.f + __expf(-2.f*v)) - 1.f; }
__device__ __forceinline__ uint32_t smem_u32(const void* p) {
    uint32_t a;
    asm("{ .reg .u64 t; cvta.to.shared.u64 t, %1; cvt.u32.u64 %0, t; }" : "=r"(a) : "l"(p));
    return a;
}
// inverse of the frag interleave: dest slot j' (0..15) -> source k-in-16
__device__ __forceinline__ int invp(int jp) {
    int t4 = jp >> 2, pos = jp & 3;
    return 2 * t4 + (pos & 1) + 8 * (pos >> 1);
}

// ---------------------------------------------------------------------------
// Pre-kernel 1: x [b][cin][t] -> xT [b][t][cin'] fp16, k-interleaved per 16.
//   64 t x 32 cin tiles; uint4 stores (4 half2 per thread per row).
// ---------------------------------------------------------------------------
__global__ __launch_bounds__(256)
void k_xprep(const float* __restrict__ x)
{
    __shared__ float s[32][65];
    const int t0 = blockIdx.x * 64, c0 = blockIdx.y * 32, b = blockIdx.z;

    #pragma unroll
    for (int i = 0; i < 8; i++) {
        int e = threadIdx.x + i * 256;      // 2048 = 32 cin-rows x 64 t
        int r = e >> 6, c = e & 63;
        s[r][c] = x[((size_t)(b * CIN + c0 + r)) * TT + t0 + c];
    }
    __syncthreads();

    const int trow = threadIdx.x >> 2;      // 0..63
    const int part = threadIdx.x & 3;       // 0..3 (uint4 within 32-cin row)
    uint32_t w[4];
    #pragma unroll
    for (int j = 0; j < 4; j++) {
        int ms = part * 4 + j;
        int grp = ms >> 3, jp = (2 * ms) & 15;
        int c0s = grp * 16 + invp(jp);
        int c1s = grp * 16 + invp(jp + 1);
        __half2 v = __floats2half2_rn(s[c0s][trow], s[c1s][trow]);
        w[j] = *(uint32_t*)&v;
    }
    *(uint4*)((__half2*)xT + ((((size_t)(b * TT + t0 + trow)) * CIN + c0) >> 1) + part * 4)
        = make_uint4(w[0], w[1], w[2], w[3]);
}

// ---------------------------------------------------------------------------
// Pre-kernel 2: W -> Wp with GATE-INTERLEAVED rows (proven): within each warp
//   32-row block, row = gate*8 + oc3.
// ---------------------------------------------------------------------------
__global__ __launch_bounds__(256)
void k_wprep(const float* __restrict__ W)
{
    const int kt = blockIdx.x, y = blockIdx.y;
    __half2* dst = (__half2*)(Wp + ((size_t)(y * 16 + kt) << 12));
    #pragma unroll
    for (int i = 0; i < 8; i++) {
        int sl = threadIdx.x + i * 256;       // 2048 u32 slots: 128 m x 16
        int m = sl >> 4, ms = sl & 15;
        int grp = ms >> 3, jp = (2 * ms) & 15;
        int wm = m >> 5, lr = m & 31;
        int gate = lr >> 3, oc3 = lr & 7;
        int wrow = gate * 256 + y * 32 + wm * 8 + oc3;
        int kk0 = kt * 32 + grp * 16 + invp(jp);
        int kk1 = kt * 32 + grp * 16 + invp(jp + 1);
        float v0 = W[wrow * 512 + ((kk0 & 255) << 1) + (kk0 >> 8)];
        float v1 = W[wrow * 512 + ((kk1 & 255) << 1) + (kk1 >> 8)];
        dst[sl] = __floats2half2_rn(v0, v1);
    }
}

// ---------------------------------------------------------------------------
// Kernel 3: PERSISTENT fp16 mma.sync GEMM, register-local gate combine
//   (byte-for-byte the R16-proven version).
// ---------------------------------------------------------------------------
__global__ __launch_bounds__(256, 2)
void qrnn_gemm(const float* __restrict__ bias)
{
    extern __shared__ char smem[];

    const int tid    = threadIdx.x;
    const int lane   = tid & 31;
    const int wid    = tid >> 5;
    const int warp_m = wid >> 1;
    const int warp_n = wid & 1;
    const int g4     = lane >> 2;
    const int t4     = lane & 3;
    const int cta    = blockIdx.x;
    const int oc_l   = warp_m * 8 + g4;   // tile-local output channel (0..31)

    #define PREFETCH(Q) do {                                                    \
        const int q_ = (Q);                                                     \
        const int tile_ = cta + (q_ >> 3) * GRID;                               \
        const int kt_ = q_ & 7;                                                 \
        const int y_ = tile_ & 7;                                               \
        const int nt_ = tile_ >> 3;                                             \
        const int b_ = nt_ >> 5;                                                \
        const int t0_ = (nt_ & 31) * BN;                                        \
        char* stA_ = smem + (q_ & 1) * STAGEB;                                  \
        char* stB_ = stA_ + BM * ROWB;                                          \
        const __half* wc_ = Wp + ((size_t)(y_ * 16 + 2 * kt_) << 12);           \
        const int tap_  = (kt_ < 4) ? 1 : 0;                                    \
        const int cin0_ = (kt_ & 3) * 64;                                       \
        _Pragma("unroll")                                                       \
        for (int i_ = 0; i_ < 8; i_++) {                                        \
            int u_ = tid + i_ * 256;                                            \
            if (u_ < 1024) {                                                    \
                int r_ = u_ >> 3, cu_ = u_ & 7;                                 \
                int scu_ = cu_ ^ ((r_ & 3) << 1);                               \
                uint32_t da_ = smem_u32(stA_ + r_ * ROWB + scu_ * 16);          \
                const __half* src_ = wc_ + ((cu_ >> 2) << 12) + r_ * 32 + (cu_ & 3) * 8; \
                asm volatile("cp.async.cg.shared.global [%0], [%1], 16;"        \
                    :: "r"(da_), "l"(src_) : "memory");                         \
            } else {                                                            \
                int v_ = u_ - 1024, r_ = v_ >> 3, cu_ = v_ & 7;                 \
                int scu_ = cu_ ^ ((r_ & 3) << 1);                               \
                uint32_t db_ = smem_u32(stB_ + r_ * ROWB + scu_ * 16);          \
                int tg_ = t0_ + r_ - tap_;                                      \
                int sz_ = (tg_ >= 0) ? 16 : 0;                                  \
                const __half* src_ = xT + ((size_t)(b_ * TT + tg_) * CIN + cin0_ + cu_ * 8); \
                asm volatile("cp.async.cg.shared.global [%0], [%1], 16, %2;"    \
                    :: "r"(db_), "l"(src_), "r"(sz_) : "memory");               \
            }                                                                   \
        }                                                                       \
        asm volatile("cp.async.commit_group;" ::: "memory");                    \
    } while (0)

    int q = 0;
    PREFETCH(0);

    #pragma unroll 1
    for (int tile = cta; tile < NTILES; tile += GRID) {
        const int y   = tile & 7;
        const int nt  = tile >> 3;
        const int b   = nt >> 5;
        const int t0  = (nt & 31) * BN;
        const int oc  = y * 32 + oc_l;

        const float bz = bias[      oc];
        const float bf = bias[256 + oc];
        const float bo = bias[512 + oc];
        const float bi = bias[768 + oc];

        float acc[2][8][4];
        #pragma unroll
        for (int im = 0; im < 2; im++)
            #pragma unroll
            for (int in = 0; in < 8; in++)
                #pragma unroll
                for (int ci = 0; ci < 4; ci++) acc[im][in][ci] = 0.f;

        #pragma unroll 1
        for (int kt = 0; kt < 8; kt++, q++) {
            asm volatile("cp.async.wait_group 0;" ::: "memory");
            __syncthreads();
            const bool more = (kt < 7) || (tile + GRID < NTILES);
            if (more) PREFETCH(q + 1);

            const char* As = smem + (q & 1) * STAGEB;
            const char* Bs = As + BM * ROWB;
            const int row0 = warp_m * 32 + g4;
            const int col0 = warp_n * 64 + g4;
            const int g3   = g4 & 3;
            const int wofs = (t4 >> 1) * 16 + (t4 & 1) * 8;

            #pragma unroll
            for (int s = 0; s < 4; s++) {
                const int kb = ((s ^ g3) << 5) + wofs;
                uint2 a00 = *(const uint2*)(As + (row0     ) * ROWB + kb);
                uint2 a08 = *(const uint2*)(As + (row0 +  8) * ROWB + kb);
                uint2 a16 = *(const uint2*)(As + (row0 + 16) * ROWB + kb);
                uint2 a24 = *(const uint2*)(As + (row0 + 24) * ROWB + kb);
                uint2 bv[8];
                #pragma unroll
                for (int in = 0; in < 8; in++)
                    bv[in] = *(const uint2*)(Bs + (col0 + in * 8) * ROWB + kb);
                #pragma unroll
                for (int in = 0; in < 8; in++) {
                    asm volatile(
                        "mma.sync.aligned.m16n8k16.row.col.f32.f16.f16.f32 "
                        "{%0,%1,%2,%3}, {%4,%5,%6,%7}, {%8,%9}, {%0,%1,%2,%3};\n"
                        : "+f"(acc[0][in][0]), "+f"(acc[0][in][1]),
                          "+f"(acc[0][in][2]), "+f"(acc[0][in][3])
                        : "r"(a00.x), "r"(a08.x), "r"(a00.y), "r"(a08.y),
                          "r"(bv[in].x), "r"(bv[in].y));
                    asm volatile(
                        "mma.sync.aligned.m16n8k16.row.col.f32.f16.f16.f32 "
                        "{%0,%1,%2,%3}, {%4,%5,%6,%7}, {%8,%9}, {%0,%1,%2,%3};\n"
                        : "+f"(acc[1][in][0]), "+f"(acc[1][in][1]),
                          "+f"(acc[1][in][2]), "+f"(acc[1][in][3])
                        : "r"(a16.x), "r"(a24.x), "r"(a16.y), "r"(a24.y),
                          "r"(bv[in].x), "r"(bv[in].y));
                }
            }
        }

        // ---- Epilogue: register-local combine, packed fp16 staging, 1 sync ----
        {
            __half2* Sfz = (__half2*)(smem + STG_FZ);
            __half*  So  = (__half*) (smem + STG_O);
            #pragma unroll
            for (int in = 0; in < 8; in++)
                #pragma unroll
                for (int p = 0; p < 2; p++) {
                    float z = tanh_acc(acc[0][in][p    ] + bz);
                    float f = sigm    (acc[0][in][2 + p] + bf);
                    float o = sigm    (acc[1][in][p    ] + bo);
                    float i = sigm    (acc[1][in][2 + p] + bi);
                    int c = warp_n * 64 + in * 8 + (t4 << 1) + p;
                    Sfz[oc_l * SST + c] = __floats2half2_rn(f, z * i);
                    So [oc_l * SST + c] = __float2half_rn(o);
                }
        }
        __syncthreads();
        {
            const __half2* Sfz = (const __half2*)(smem + STG_FZ);
            const __half*  So  = (const __half*) (smem + STG_O);
            #pragma unroll
            for (int i = 0; i < 16; i++) {
                int e = tid + i * 256;           // 4096 = 32 rows x 128 cols
                int r = e >> 7, cc = e & 127;
                g_fz[((size_t)(b * COUT + y * 32 + r)) * TT + t0 + cc] =
                    Sfz[r * SST + cc];
            }
            #pragma unroll
            for (int i = 0; i < 8; i++) {
                int e = tid + i * 256;           // 2048 = 32 rows x 64 pairs
                int r = e >> 6, cu = e & 63;
                *(__half2*)(g_o + ((size_t)(b * COUT + y * 32 + r)) * TT + t0 + cu * 2) =
                    *(const __half2*)(So + r * SST + cu * 2);
            }
        }
        // next tile's first-chunk sync doubles as the closing barrier
    }
    #undef PREFETCH
}

// ---------------------------------------------------------------------------
// Kernel 4: linear recurrence scan over fp16 packed gates.
//   256 thr x 16 elems (proven). o-loads hoisted above the serial chain;
//   streaming loads (.cs) for gates, streaming stores (.cs) for output.
// ---------------------------------------------------------------------------
__global__ __launch_bounds__(256)
void qrnn_scan(float* __restrict__ out)
{
    __shared__ float wa[8], wb[8];

    const int tid  = threadIdx.x;
    const int lane = tid & 31;
    const int wrp  = tid >> 5;
    const size_t my = (size_t)blockIdx.x * TT + tid * 16;

    // issue ALL loads up front (6 independent 16B loads in flight)
    uint4 v0 = __ldcs((const uint4*)(g_fz + my) + 0);
    uint4 v1 = __ldcs((const uint4*)(g_fz + my) + 1);
    uint4 v2 = __ldcs((const uint4*)(g_fz + my) + 2);
    uint4 v3 = __ldcs((const uint4*)(g_fz + my) + 3);
    uint4 o0 = __ldcs((const uint4*)(g_o + my) + 0);
    uint4 o1 = __ldcs((const uint4*)(g_o + my) + 1);

    float f[16], z[16];
    {
        uint4 vv[4] = { v0, v1, v2, v3 };
        #pragma unroll
        for (int q = 0; q < 4; q++) {
            float2 p0 = __half22float2(*(const __half2*)&vv[q].x);
            float2 p1 = __half22float2(*(const __half2*)&vv[q].y);
            float2 p2 = __half22float2(*(const __half2*)&vv[q].z);
            float2 p3 = __half22float2(*(const __half2*)&vv[q].w);
            f[q*4+0] = p0.x; z[q*4+0] = p0.y;
            f[q*4+1] = p1.x; z[q*4+1] = p1.y;
            f[q*4+2] = p2.x; z[q*4+2] = p2.y;
            f[q*4+3] = p3.x; z[q*4+3] = p3.y;
        }
    }

    float a = 1.f, bb = 0.f;
    #pragma unroll
    for (int j = 0; j < 16; j++) { a *= f[j]; bb = f[j] * bb + z[j]; }

    #pragma unroll
    for (int d = 1; d < 32; d <<= 1) {
        float ua = __shfl_up_sync(0xffffffffu, a,  d);
        float ub = __shfl_up_sync(0xffffffffu, bb, d);
        if (lane >= d) { bb = a * ub + bb; a = a * ua; }
    }
    if (lane == 31) { wa[wrp] = a; wb[wrp] = bb; }
    __syncthreads();
    float pb = 0.f;
    #pragma unroll
    for (int w = 0; w < 7; w++)
        if (w < wrp) pb = wa[w] * pb + wb[w];
    float ea = __shfl_up_sync(0xffffffffu, a,  1);
    float eb = __shfl_up_sync(0xffffffffu, bb, 1);
    if (lane == 0) { ea = 1.f; eb = 0.f; }
    float c = ea * pb + eb;              // carry into this chunk (c_init = 0)

    #pragma unroll
    for (int j = 0; j < 16; j++) { c = f[j] * c + z[j]; f[j] = c; }

    float ov[16];
    {
        const uint32_t* w0 = (const uint32_t*)&o0;
        const uint32_t* w1 = (const uint32_t*)&o1;
        #pragma unroll
        for (int q = 0; q < 4; q++) {
            float2 p = __half22float2(*(const __half2*)&w0[q]);
            ov[q*2+0] = p.x; ov[q*2+1] = p.y;
        }
        #pragma unroll
        for (int q = 0; q < 4; q++) {
            float2 p = __half22float2(*(const __half2*)&w1[q]);
            ov[8+q*2+0] = p.x; ov[8+q*2+1] = p.y;
        }
    }

    #pragma unroll
    for (int j = 0; j < 4; j++) {
        float4 r;
        r.x = ov[j*4+0] * f[j*4+0]; r.y = ov[j*4+1] * f[j*4+1];
        r.z = ov[j*4+2] * f[j*4+2]; r.w = ov[j*4+3] * f[j*4+3];
        __stcs((float4*)(out + my) + j, r);
    }
}

extern "C" void kernel_launch(void* const* d_in, const int* in_sizes, int n_in,
                              void* d_out, int out_size)
{
    const float* x    = (const float*)d_in[0];  // [8, 256, 4096]
    const float* W    = (const float*)d_in[1];  // [1024, 256, 2]
    const float* bias = (const float*)d_in[2];  // [1024]
    float* out = (float*)d_out;                 // [8, 256, 4096]

    static int smem_set = 0;
    if (!smem_set) {
        cudaFuncSetAttribute(qrnn_gemm, cudaFuncAttributeMaxDynamicSharedMemorySize, GEMM_SMEM);
        smem_set = 1;
    }

    k_xprep<<<dim3(TT / 64, CIN / 32, BBATCH), 256>>>(x);
    k_wprep<<<dim3(16, 8), 256>>>(W);
    qrnn_gemm<<<GRID, 256, GEMM_SMEM>>>(bias);
    qrnn_scan<<<BBATCH * COUT, 256>>>(out);
}